// round 11
// baseline (speedup 1.0000x reference)
#include <cuda_runtime.h>
#include <cstdint>

#define CC 20
#define NCELLS (16384 * 7 * 7)         // 802816 = 6272 * 128
#define CELLS_PER_BLOCK 128
#define NBLOCKS (NCELLS / CELLS_PER_BLOCK)   // 6272
#define PRED_STRIDE 30
#define TGT_STRIDE 25
#define LAMBDA_COORD 5.0f
#define LAMBDA_NOOBJ 0.5f
#define EPS_W 1e-6f
#define IOU_EPS 1e-6f
#define INV_BATCH (1.0 / 16384.0)

#define PRED_F4_PER_BLOCK (CELLS_PER_BLOCK * PRED_STRIDE / 4)   // 960
#define TGT_F4_PER_BLOCK  (CELLS_PER_BLOCK * TGT_STRIDE  / 4)   // 800

// Per-block partial sums: written unconditionally every launch -> no zeroing,
// no atomics, graph-replay idempotent.
__device__ double g_partial[NBLOCKS];

__device__ __forceinline__ void cp_async16(uint32_t smem_addr, const void* gptr) {
    asm volatile("cp.async.cg.shared.global [%0], [%1], 16;"
                 :: "r"(smem_addr), "l"(gptr) : "memory");
}

__device__ __forceinline__ float iou_box(float ax, float ay, float aw, float ah,
                                         float bx, float by, float bw, float bh) {
    float ax1 = ax - aw * 0.5f, ax2 = ax + aw * 0.5f;
    float ay1 = ay - ah * 0.5f, ay2 = ay + ah * 0.5f;
    float bx1 = bx - bw * 0.5f, bx2 = bx + bw * 0.5f;
    float by1 = by - bh * 0.5f, by2 = by + bh * 0.5f;
    float iw = fmaxf(fminf(ax2, bx2) - fmaxf(ax1, bx1), 0.0f);
    float ih = fmaxf(fminf(ay2, by2) - fmaxf(ay1, by1), 0.0f);
    float inter = iw * ih;
    float area_a = fabsf(aw * ah);
    float area_b = fabsf(bw * bh);
    return inter / (area_a + area_b - inter + IOU_EPS);
}

__global__ void __launch_bounds__(CELLS_PER_BLOCK, 8)
yolo_loss_kernel(const float* __restrict__ pred, const float* __restrict__ tgt) {
    __shared__ float sp[CELLS_PER_BLOCK * PRED_STRIDE];   // 15360 B
    __shared__ float st[CELLS_PER_BLOCK * TGT_STRIDE];    // 12800 B

    const int tid = threadIdx.x;
    const int bid = blockIdx.x;

    // ---- Stage: cp.async GMEM -> SMEM, no register round-trip ----
    {
        const float4* psrc = reinterpret_cast<const float4*>(
            pred + (size_t)bid * CELLS_PER_BLOCK * PRED_STRIDE);
        uint32_t sp_base = (uint32_t)__cvta_generic_to_shared(sp);
        #pragma unroll
        for (int i = tid; i < PRED_F4_PER_BLOCK; i += CELLS_PER_BLOCK)
            cp_async16(sp_base + i * 16, psrc + i);

        const float4* tsrc = reinterpret_cast<const float4*>(
            tgt + (size_t)bid * CELLS_PER_BLOCK * TGT_STRIDE);
        uint32_t st_base = (uint32_t)__cvta_generic_to_shared(st);
        #pragma unroll
        for (int i = tid; i < TGT_F4_PER_BLOCK; i += CELLS_PER_BLOCK)
            cp_async16(st_base + i * 16, tsrc + i);

        asm volatile("cp.async.commit_group;" ::: "memory");
        asm volatile("cp.async.wait_group 0;" ::: "memory");
    }
    __syncthreads();

    // ---- Compute: one thread = one cell, operands from smem ----
    const float* p = sp + tid * PRED_STRIDE;
    const float* t = st + tid * TGT_STRIDE;

    float cls = 0.0f;
    #pragma unroll
    for (int i = 0; i < CC; i++) {
        float d = p[i] - t[i];
        cls = fmaf(d, d, cls);
    }

    float b1x = p[20], b1y = p[21], b1w = p[22], b1h = p[23], b1c = p[24];
    float b2x = p[25], b2y = p[26], b2w = p[27], b2h = p[28], b2c = p[29];
    // tb = targets[..., 20:25] : note tb.x IS the objectness flag column
    float tbx = t[20], tby = t[21], tbw = t[22], tbh = t[23], tbc = t[24];
    float obj = (tbx == 1.0f) ? 1.0f : 0.0f;

    float iou1 = iou_box(b1x, b1y, b1w, b1h, tbx, tby, tbw, tbh);
    float iou2 = iou_box(b2x, b2y, b2w, b2h, tbx, tby, tbw, tbh);
    bool use1 = iou1 > iou2;

    float rx = use1 ? b1x : b2x;
    float ry = use1 ? b1y : b2y;
    float rw = use1 ? b1w : b2w;
    float rh = use1 ? b1h : b2h;
    float rc = use1 ? b1c : b2c;
    float other_conf = use1 ? b2c : b1c;

    float dx = rx - tbx;
    float dy = ry - tby;
    float dw = sqrtf(fmaxf(rw, EPS_W)) - sqrtf(fmaxf(tbw, EPS_W));
    float dh = sqrtf(fmaxf(rh, EPS_W)) - sqrtf(fmaxf(tbh, EPS_W));
    float coord = LAMBDA_COORD * (dx * dx + dy * dy + dw * dw + dh * dh);

    float dconf = rc - tbc;
    float obj_conf = dconf * dconf;
    float noobj_in = LAMBDA_NOOBJ * other_conf * other_conf;
    float noobj_out = LAMBDA_NOOBJ * (b1c * b1c + b2c * b2c);

    float loss = obj * (coord + obj_conf + cls + noobj_in) + (1.0f - obj) * noobj_out;

    // ---- Block reduction ----
    #pragma unroll
    for (int o = 16; o > 0; o >>= 1)
        loss += __shfl_xor_sync(0xffffffffu, loss, o);

    __shared__ float warp_sums[4];
    int lane = tid & 31;
    int wid = tid >> 5;
    if (lane == 0) warp_sums[wid] = loss;
    __syncthreads();

    if (wid == 0) {
        float s = (lane < 4) ? warp_sums[lane] : 0.0f;
        #pragma unroll
        for (int o = 2; o > 0; o >>= 1)
            s += __shfl_xor_sync(0xffffffffu, s, o);
        if (lane == 0)
            g_partial[bid] = (double)s;   // unconditional write, no atomic
    }
}

__global__ void __launch_bounds__(512)
finalize_kernel(float* out) {
    // PDL: launch/setup overlapped with producer grid tail; block until the
    // producer grid (and its global writes) are complete before reading.
    cudaGridDependencySynchronize();

    const int tid = threadIdx.x;

    // 6272 = 512*12 + 128. 12 strided loads per thread split across 4
    // independent accumulators (serial depth 3 -> latency overlapped).
    double a0 = 0.0, a1 = 0.0, a2 = 0.0, a3 = 0.0;
    #pragma unroll
    for (int k = 0; k < 12; k += 4) {
        a0 += g_partial[tid + (k + 0) * 512];
        a1 += g_partial[tid + (k + 1) * 512];
        a2 += g_partial[tid + (k + 2) * 512];
        a3 += g_partial[tid + (k + 3) * 512];
    }
    if (tid < 128) a0 += g_partial[6144 + tid];
    double s = (a0 + a1) + (a2 + a3);

    #pragma unroll
    for (int o = 16; o > 0; o >>= 1)
        s += __shfl_xor_sync(0xffffffffu, s, o);

    __shared__ double wsum[16];
    int lane = tid & 31;
    int wid = tid >> 5;
    if (lane == 0) wsum[wid] = s;
    __syncthreads();

    if (tid == 0) {
        double total = 0.0;
        #pragma unroll
        for (int w = 0; w < 16; w++) total += wsum[w];
        out[0] = (float)(total * INV_BATCH);
    }
}

extern "C" void kernel_launch(void* const* d_in, const int* in_sizes, int n_in,
                              void* d_out, int out_size) {
    const float* pred = (const float*)d_in[0];
    const float* tgt  = (const float*)d_in[1];
    float* out = (float*)d_out;

    yolo_loss_kernel<<<NBLOCKS, CELLS_PER_BLOCK>>>(pred, tgt);

    // Finalize with programmatic dependent launch: overlaps its launch with
    // the main grid's tail; cudaGridDependencySynchronize() inside provides
    // the ordering.
    cudaLaunchConfig_t cfg = {};
    cfg.gridDim = dim3(1, 1, 1);
    cfg.blockDim = dim3(512, 1, 1);
    cfg.dynamicSmemBytes = 0;
    cfg.stream = 0;
    cudaLaunchAttribute attr;
    attr.id = cudaLaunchAttributeProgrammaticStreamSerialization;
    attr.val.programmaticStreamSerializationAllowed = 1;
    cfg.attrs = &attr;
    cfg.numAttrs = 1;
    cudaLaunchKernelEx(&cfg, finalize_kernel, out);
}